// round 2
// baseline (speedup 1.0000x reference)
#include <cuda_runtime.h>
#include <stdint.h>

#define NODES 50000
#define DD 64
#define BM 128

typedef unsigned long long ull;

// ---------------- scratch ----------------
__device__ __align__(16) float g_ha[NODES * DD];   // x @ W1[0:64] + b1   (dst half)
__device__ __align__(16) float g_hb[NODES * DD];   // x @ W1[64:128]      (src half)
__device__ __align__(16) float g_S[NODES * DD];    // sum over edges of relu(ha[dst]+hb[src])
__device__ __align__(16) float g_deg[NODES];       // in-degree
__device__ int g_is64;

// packed dual-fp32 FMA (Blackwell FFMA2; ptxas never emits this from C++)
__device__ __forceinline__ void ffma2(ull& d, ull a, ull b) {
    asm("fma.rn.f32x2 %0, %1, %2, %0;" : "+l"(d) : "l"(a), "l"(b));
}
union F2U { ull u; float2 f; };

// ---------------- edge_index dtype detection ----------------
__global__ void detect_kernel(const void* __restrict__ idx) {
    const int* p = (const int*)idx;
    int is64 = 1;
    for (int i = 0; i < 16; i++) {
        int lo = p[2 * i], hi = p[2 * i + 1];
        if (hi != 0 || lo < 0 || lo >= NODES) is64 = 0;
    }
    g_is64 = is64;
}

// ---------------- zero accumulators ----------------
__global__ void zero_kernel() {
    int i = blockIdx.x * blockDim.x + threadIdx.x;
    int stride = gridDim.x * blockDim.x;
    for (int j = i; j < NODES * DD; j += stride) g_S[j] = 0.0f;
    for (int j = i; j < NODES; j += stride) g_deg[j] = 0.0f;
}

// ================= PRE: ha = x@W1a + b1 ; hb = x@W1b =================
// BM=128 rows/block, 256 threads, 8x8 outputs/thread over 128x128 output tile.
// x tile stored transposed + duplicated: xT[k][2r]=xT[k][2r+1]=x[r][k], so
// ld.shared.v2.u64 yields ready (a,a) f32x2 pairs. W pairs are contiguous.
__global__ __launch_bounds__(256, 2) void pre_kernel(
    const float* __restrict__ x, const float* __restrict__ W1,
    const float* __restrict__ b1, int n)
{
    extern __shared__ float sm[];
    float* xT = sm;            // [64][264]  (2*BM + 8 pad)
    float* Ws = sm + 64 * 264; // [64][132]  combined [k][cc]: cc<64 -> ha, cc>=64 -> hb

    const int tid = threadIdx.x;
    const int row0 = blockIdx.x * BM;

    // weights: W1 is [128][64]; rows 0..63 -> ha cols, rows 64..127 -> hb cols
    for (int i = tid; i < 2048; i += 256) {
        int kk = i >> 4;
        int c4 = (i & 15) * 4;
        float4 v = *(const float4*)(W1 + kk * 64 + c4);
        int k = kk & 63;
        int cc = (kk < 64) ? c4 : (64 + c4);
        *(float4*)&Ws[k * 132 + cc] = v;
    }
    // x tile transposed + duplicated
    {
        int r = tid >> 1;
        int ks = (tid & 1) * 32;
        int gr = row0 + r;
#pragma unroll
        for (int q = 0; q < 8; q++) {
            float4 v = make_float4(0.f, 0.f, 0.f, 0.f);
            if (gr < n) v = *(const float4*)(x + (size_t)gr * DD + ks + q * 4);
            int k = ks + q * 4;
            *(float2*)&xT[(k + 0) * 264 + 2 * r] = make_float2(v.x, v.x);
            *(float2*)&xT[(k + 1) * 264 + 2 * r] = make_float2(v.y, v.y);
            *(float2*)&xT[(k + 2) * 264 + 2 * r] = make_float2(v.z, v.z);
            *(float2*)&xT[(k + 3) * 264 + 2 * r] = make_float2(v.w, v.w);
        }
    }
    __syncthreads();

    const int ty = tid >> 4;     // 0..15
    const int tx = tid & 15;     // 0..15
    const int r2 = ty * 16;      // duplicated offset of row ty*8
    const int c0 = tx * 8;       // output cols c0..c0+7 (within 0..127)

    ull acc[8][4];
#pragma unroll
    for (int i = 0; i < 8; i++)
#pragma unroll
        for (int j = 0; j < 4; j++) acc[i][j] = 0ULL;

#pragma unroll 4
    for (int k = 0; k < 64; k++) {
        const ulonglong2* ap = (const ulonglong2*)&xT[k * 264 + r2];
        ulonglong2 a01 = ap[0], a23 = ap[1], a45 = ap[2], a67 = ap[3];
        const ulonglong2* wp = (const ulonglong2*)&Ws[k * 132 + c0];
        ulonglong2 w01 = wp[0], w23 = wp[1];
        ull A[8] = {a01.x, a01.y, a23.x, a23.y, a45.x, a45.y, a67.x, a67.y};
        ull W[4] = {w01.x, w01.y, w23.x, w23.y};
#pragma unroll
        for (int i = 0; i < 8; i++)
#pragma unroll
            for (int j = 0; j < 4; j++) ffma2(acc[i][j], A[i], W[j]);
    }

    float bb[8];
    if (c0 < 64) {
#pragma unroll
        for (int j = 0; j < 8; j++) bb[j] = b1[c0 + j];
    }
#pragma unroll
    for (int i = 0; i < 8; i++) {
        int gr = row0 + ty * 8 + i;
        if (gr >= n) break;
        F2U u0, u1, u2, u3;
        u0.u = acc[i][0]; u1.u = acc[i][1]; u2.u = acc[i][2]; u3.u = acc[i][3];
        if (c0 < 64) {
            *(float4*)(g_ha + (size_t)gr * DD + c0) =
                make_float4(u0.f.x + bb[0], u0.f.y + bb[1], u1.f.x + bb[2], u1.f.y + bb[3]);
            *(float4*)(g_ha + (size_t)gr * DD + c0 + 4) =
                make_float4(u2.f.x + bb[4], u2.f.y + bb[5], u3.f.x + bb[6], u3.f.y + bb[7]);
        } else {
            *(float4*)(g_hb + (size_t)gr * DD + (c0 - 64)) =
                make_float4(u0.f.x, u0.f.y, u1.f.x, u1.f.y);
            *(float4*)(g_hb + (size_t)gr * DD + (c0 - 64) + 4) =
                make_float4(u2.f.x, u2.f.y, u3.f.x, u3.f.y);
        }
    }
}

// ================= edge scatter: S[dst] += relu(ha[dst]+hb[src]) =================
__launch_bounds__(256)
__global__ void edge_kernel(const void* __restrict__ eidx, int E) {
    const int t = blockIdx.x * blockDim.x + threadIdx.x;
    const int e = t >> 4;
    if (e >= E) return;
    const int lane = t & 15;

    int src, dst;
    if (g_is64) {
        const long long* p = (const long long*)eidx;
        src = (int)__ldg(&p[e]);
        dst = (int)__ldg(&p[E + e]);
    } else {
        const int* p = (const int*)eidx;
        src = __ldg(&p[e]);
        dst = __ldg(&p[E + e]);
    }

    const float4 a = __ldg((const float4*)(g_ha + (size_t)dst * DD) + lane);
    const float4 b = __ldg((const float4*)(g_hb + (size_t)src * DD) + lane);
    float4 v;
    v.x = fmaxf(a.x + b.x, 0.f);
    v.y = fmaxf(a.y + b.y, 0.f);
    v.z = fmaxf(a.z + b.z, 0.f);
    v.w = fmaxf(a.w + b.w, 0.f);

    float* p = g_S + (size_t)dst * DD + lane * 4;
    asm volatile("red.global.add.v4.f32 [%0], {%1, %2, %3, %4};"
                 :: "l"(p), "f"(v.x), "f"(v.y), "f"(v.z), "f"(v.w)
                 : "memory");

    if (lane == 0) atomicAdd(&g_deg[dst], 1.0f);
}

// ================= POST: aggr=S@W2+deg*b2; hid=relu([x,aggr]@U1+ub1); out=hid@U2+ub2 =================
// BM=128 rows/block, 256 threads, 4x8 outputs/thread per stage. All three
// stages chained through smem; buf0: S-T -> aggr-T, buf1: x-T -> hid-T.
__global__ __launch_bounds__(256, 1) void post_kernel(
    const float* __restrict__ x,
    const float* __restrict__ W2, const float* __restrict__ b2,
    const float* __restrict__ U1, const float* __restrict__ ub1,
    const float* __restrict__ U2, const float* __restrict__ ub2,
    float* __restrict__ out, int n)
{
    extern __shared__ float sm[];
    float* buf0 = sm;                // [64][264]
    float* buf1 = sm + 16896;        // [64][264]
    float* W2s  = sm + 2 * 16896;    // [64][68]
    float* U1a  = W2s + 4352;
    float* U1b  = U1a + 4352;
    float* U2s  = U1b + 4352;

    const int tid = threadIdx.x;
    const int row0 = blockIdx.x * BM;

    // weights
    for (int i = tid; i < 1024; i += 256) {
        int k = i >> 4;
        int c4 = (i & 15) * 4;
        *(float4*)&W2s[k * 68 + c4] = *(const float4*)(W2 + k * 64 + c4);
        *(float4*)&U1a[k * 68 + c4] = *(const float4*)(U1 + k * 64 + c4);
        *(float4*)&U1b[k * 68 + c4] = *(const float4*)(U1 + (64 + k) * 64 + c4);
        *(float4*)&U2s[k * 68 + c4] = *(const float4*)(U2 + k * 64 + c4);
    }
    // tiles: buf0 <- S (transposed+dup), buf1 <- x
    {
        int r = tid >> 1;
        int ks = (tid & 1) * 32;
        int gr = row0 + r;
#pragma unroll
        for (int q = 0; q < 8; q++) {
            float4 vs = make_float4(0.f, 0.f, 0.f, 0.f);
            float4 vx = vs;
            if (gr < n) {
                vs = *(const float4*)(g_S + (size_t)gr * DD + ks + q * 4);
                vx = *(const float4*)(x + (size_t)gr * DD + ks + q * 4);
            }
            int k = ks + q * 4;
            *(float2*)&buf0[(k + 0) * 264 + 2 * r] = make_float2(vs.x, vs.x);
            *(float2*)&buf0[(k + 1) * 264 + 2 * r] = make_float2(vs.y, vs.y);
            *(float2*)&buf0[(k + 2) * 264 + 2 * r] = make_float2(vs.z, vs.z);
            *(float2*)&buf0[(k + 3) * 264 + 2 * r] = make_float2(vs.w, vs.w);
            *(float2*)&buf1[(k + 0) * 264 + 2 * r] = make_float2(vx.x, vx.x);
            *(float2*)&buf1[(k + 1) * 264 + 2 * r] = make_float2(vx.y, vx.y);
            *(float2*)&buf1[(k + 2) * 264 + 2 * r] = make_float2(vx.z, vx.z);
            *(float2*)&buf1[(k + 3) * 264 + 2 * r] = make_float2(vx.w, vx.w);
        }
    }
    __syncthreads();

    const int ty = tid >> 3;   // 0..31
    const int tx = tid & 7;    // 0..7
    const int r0 = ty * 4;
    const int r2 = ty * 8;     // duplicated offset
    const int c0 = tx * 8;

    ull acc[4][4];

    // ---------- stage 1: aggr = S @ W2  (+ deg*b2 in epilogue) ----------
#pragma unroll
    for (int i = 0; i < 4; i++)
#pragma unroll
        for (int j = 0; j < 4; j++) acc[i][j] = 0ULL;
#pragma unroll 4
    for (int k = 0; k < 64; k++) {
        const ulonglong2* ap = (const ulonglong2*)&buf0[k * 264 + r2];
        ulonglong2 a01 = ap[0], a23 = ap[1];
        const ulonglong2* wp = (const ulonglong2*)&W2s[k * 68 + c0];
        ulonglong2 w01 = wp[0], w23 = wp[1];
        ull A[4] = {a01.x, a01.y, a23.x, a23.y};
        ull W[4] = {w01.x, w01.y, w23.x, w23.y};
#pragma unroll
        for (int i = 0; i < 4; i++)
#pragma unroll
            for (int j = 0; j < 4; j++) ffma2(acc[i][j], A[i], W[j]);
    }
    __syncthreads();
    {
        float dg[4];
#pragma unroll
        for (int i = 0; i < 4; i++) {
            int gr = row0 + r0 + i;
            dg[i] = (gr < n) ? g_deg[gr] : 0.f;
        }
#pragma unroll
        for (int j = 0; j < 4; j++) {
            float ba = b2[c0 + 2 * j], bbb = b2[c0 + 2 * j + 1];
#pragma unroll
            for (int i = 0; i < 4; i++) {
                F2U u; u.u = acc[i][j];
                float va = u.f.x + ba * dg[i];
                float vb = u.f.y + bbb * dg[i];
                *(float2*)&buf0[(c0 + 2 * j) * 264 + 2 * (r0 + i)] = make_float2(va, va);
                *(float2*)&buf0[(c0 + 2 * j + 1) * 264 + 2 * (r0 + i)] = make_float2(vb, vb);
            }
        }
    }
    __syncthreads();

    // ---------- stage 2: hid = relu(x@U1a + aggr@U1b + ub1) ----------
#pragma unroll
    for (int i = 0; i < 4; i++)
#pragma unroll
        for (int j = 0; j < 4; j++) acc[i][j] = 0ULL;
#pragma unroll 2
    for (int k = 0; k < 64; k++) {
        const ulonglong2* ap = (const ulonglong2*)&buf1[k * 264 + r2];
        ulonglong2 a01 = ap[0], a23 = ap[1];
        const ulonglong2* wp = (const ulonglong2*)&U1a[k * 68 + c0];
        ulonglong2 w01 = wp[0], w23 = wp[1];
        ull A[4] = {a01.x, a01.y, a23.x, a23.y};
        ull W[4] = {w01.x, w01.y, w23.x, w23.y};
#pragma unroll
        for (int i = 0; i < 4; i++)
#pragma unroll
            for (int j = 0; j < 4; j++) ffma2(acc[i][j], A[i], W[j]);
        const ulonglong2* bp = (const ulonglong2*)&buf0[k * 264 + r2];
        ulonglong2 b01 = bp[0], b23 = bp[1];
        const ulonglong2* vp = (const ulonglong2*)&U1b[k * 68 + c0];
        ulonglong2 v01 = vp[0], v23 = vp[1];
        ull B[4] = {b01.x, b01.y, b23.x, b23.y};
        ull V[4] = {v01.x, v01.y, v23.x, v23.y};
#pragma unroll
        for (int i = 0; i < 4; i++)
#pragma unroll
            for (int j = 0; j < 4; j++) ffma2(acc[i][j], B[i], V[j]);
    }
    __syncthreads();
    {
#pragma unroll
        for (int j = 0; j < 4; j++) {
            float ba = ub1[c0 + 2 * j], bbb = ub1[c0 + 2 * j + 1];
#pragma unroll
            for (int i = 0; i < 4; i++) {
                F2U u; u.u = acc[i][j];
                float va = fmaxf(u.f.x + ba, 0.f);
                float vb = fmaxf(u.f.y + bbb, 0.f);
                *(float2*)&buf1[(c0 + 2 * j) * 264 + 2 * (r0 + i)] = make_float2(va, va);
                *(float2*)&buf1[(c0 + 2 * j + 1) * 264 + 2 * (r0 + i)] = make_float2(vb, vb);
            }
        }
    }
    __syncthreads();

    // ---------- stage 3: out = hid @ U2 + ub2 ----------
#pragma unroll
    for (int i = 0; i < 4; i++)
#pragma unroll
        for (int j = 0; j < 4; j++) acc[i][j] = 0ULL;
#pragma unroll 4
    for (int k = 0; k < 64; k++) {
        const ulonglong2* ap = (const ulonglong2*)&buf1[k * 264 + r2];
        ulonglong2 a01 = ap[0], a23 = ap[1];
        const ulonglong2* wp = (const ulonglong2*)&U2s[k * 68 + c0];
        ulonglong2 w01 = wp[0], w23 = wp[1];
        ull A[4] = {a01.x, a01.y, a23.x, a23.y};
        ull W[4] = {w01.x, w01.y, w23.x, w23.y};
#pragma unroll
        for (int i = 0; i < 4; i++)
#pragma unroll
            for (int j = 0; j < 4; j++) ffma2(acc[i][j], A[i], W[j]);
    }
    {
        float ba[8];
#pragma unroll
        for (int j = 0; j < 8; j++) ba[j] = ub2[c0 + j];
#pragma unroll
        for (int i = 0; i < 4; i++) {
            int gr = row0 + r0 + i;
            if (gr >= n) break;
            F2U u0, u1, u2, u3;
            u0.u = acc[i][0]; u1.u = acc[i][1]; u2.u = acc[i][2]; u3.u = acc[i][3];
            *(float4*)(out + (size_t)gr * DD + c0) =
                make_float4(u0.f.x + ba[0], u0.f.y + ba[1], u1.f.x + ba[2], u1.f.y + ba[3]);
            *(float4*)(out + (size_t)gr * DD + c0 + 4) =
                make_float4(u2.f.x + ba[4], u2.f.y + ba[5], u3.f.x + ba[6], u3.f.y + ba[7]);
        }
    }
}

// ---------------- launch ----------------
extern "C" void kernel_launch(void* const* d_in, const int* in_sizes, int n_in,
                              void* d_out, int out_size) {
    const float* x   = (const float*)d_in[0];
    const void*  eix = d_in[1];
    const float* W1  = (const float*)d_in[2];
    const float* b1  = (const float*)d_in[3];
    const float* W2  = (const float*)d_in[4];
    const float* b2  = (const float*)d_in[5];
    const float* U1  = (const float*)d_in[6];
    const float* ub1 = (const float*)d_in[7];
    const float* U2  = (const float*)d_in[8];
    const float* ub2 = (const float*)d_in[9];
    float* out = (float*)d_out;

    const int n = in_sizes[0] / DD;   // 50000
    const int E = in_sizes[1] / 2;    // 800000

    static int attr_done = 0;
    const int PRE_SMEM  = (64 * 264 + 64 * 132) * 4;          // 101376 B
    const int POST_SMEM = (2 * 16896 + 4 * 4352) * 4;         // 204800 B
    if (!attr_done) {
        cudaFuncSetAttribute(pre_kernel,  cudaFuncAttributeMaxDynamicSharedMemorySize, PRE_SMEM);
        cudaFuncSetAttribute(post_kernel, cudaFuncAttributeMaxDynamicSharedMemorySize, POST_SMEM);
        attr_done = 1;
    }

    const int nb = (n + BM - 1) / BM;  // 391

    detect_kernel<<<1, 1>>>(eix);
    zero_kernel<<<512, 256>>>();

    pre_kernel<<<nb, 256, PRE_SMEM>>>(x, W1, b1, n);

    {
        const long long tot = (long long)E * 16;
        const int grid = (int)((tot + 255) / 256);
        edge_kernel<<<grid, 256>>>(eix, E);
    }

    post_kernel<<<nb, 256, POST_SMEM>>>(x, W2, b2, U1, ub1, U2, ub2, out, n);
}